// round 1
// baseline (speedup 1.0000x reference)
#include <cuda_runtime.h>

#define L_SEQ 2048
#define DH    64
#define BM    64
#define BN    64

// Flash attention, fp32 CUDA cores.
// Grid: (L/BM, B*H). Block: 256 threads = 16x16 (tr, tc).
// Each thread: 4x4 S fragment (rows 4*tr.., cols 4*tc..) and 4x4 O fragment
// (rows 4*tr.., head-dims 4*tc..). Online softmax state per thread: m,l for its
// 4 rows (replicated across the 16 tc lanes of that row group).
__global__ __launch_bounds__(256)
void fa_kernel(const float* __restrict__ Qg, const float* __restrict__ Kg,
               const float* __restrict__ Vg, float* __restrict__ Og) {
    __shared__ float Qs[BM][DH];   // 16 KB, loaded once
    __shared__ float Kt[DH][BN];   // K stored k-major (swizzled); reused as P[BM][BN]
    __shared__ float Vs[BN][DH];   // 16 KB

    const int tid = threadIdx.x;
    const int tr  = tid >> 4;      // 0..15 -> rows 4*tr..4*tr+3
    const int tc  = tid & 15;      // 0..15 -> cols 4*tc..4*tc+3
    const int iblk = blockIdx.x;
    const int bh   = blockIdx.y;

    const size_t base = (size_t)bh * L_SEQ * DH;
    const float* Qb = Qg + base;
    const float* Kb = Kg + base;
    const float* Vb = Vg + base;
    float*       Ob = Og + base;
    const int row0 = iblk * BM;

    // ---- Load Q tile (coalesced float4) ----
    for (int i = tid; i < BM * (DH / 4); i += 256) {
        const int r  = i >> 4;     // row 0..63
        const int c4 = i & 15;     // float4 index 0..15
        ((float4*)Qs[r])[c4] =
            ((const float4*)(Qb + (size_t)(row0 + r) * DH))[c4];
    }

    float  m_prev[4], l_run[4];
    float4 acc[4];
#pragma unroll
    for (int rr = 0; rr < 4; rr++) {
        m_prev[rr] = -1e30f;
        l_run[rr]  = 0.0f;
        acc[rr]    = make_float4(0.f, 0.f, 0.f, 0.f);
    }

    const int nblk = iblk + 1;     // causal: key blocks 0..iblk
    for (int j = 0; j < nblk; j++) {
        __syncthreads();           // prev iter done with Kt(P)/Vs; Qs visible (iter 0)
        const int col0 = j * BN;

        // ---- Load K (transposed k-major, XOR-swizzled) and V (direct) ----
        // Swizzle: logical (k, c) stored at column 4*((c>>2) ^ (k>>2)) + (c&3).
        // Read of 4 consecutive logical c at fixed k stays one aligned float4,
        // and the float4-group index is a permutation of tc -> conflict-free.
        for (int i = tid; i < BN * (DH / 4); i += 256) {
            const int r = i >> 4;          // key row (logical c), 0..63
            const int g = i & 15;          // k-group: k = 4g..4g+3
            const float4 kv =
                ((const float4*)(Kb + (size_t)(col0 + r) * DH))[g];
            const int pc = 4 * ((r >> 2) ^ g) + (r & 3);
            Kt[4 * g + 0][pc] = kv.x;
            Kt[4 * g + 1][pc] = kv.y;
            Kt[4 * g + 2][pc] = kv.z;
            Kt[4 * g + 3][pc] = kv.w;
            ((float4*)Vs[r])[g] =
                ((const float4*)(Vb + (size_t)(col0 + r) * DH))[g];
        }
        __syncthreads();

        // ---- S = Q * K^T fragment ----
        float s[4][4];
#pragma unroll
        for (int rr = 0; rr < 4; rr++)
#pragma unroll
            for (int cc = 0; cc < 4; cc++) s[rr][cc] = 0.f;

#pragma unroll 8
        for (int k = 0; k < DH; k++) {
            const float4 kf =
                *(const float4*)&Kt[k][4 * (tc ^ (k >> 2))];
            const float q0 = Qs[4 * tr + 0][k];
            const float q1 = Qs[4 * tr + 1][k];
            const float q2 = Qs[4 * tr + 2][k];
            const float q3 = Qs[4 * tr + 3][k];
            s[0][0] += q0 * kf.x; s[0][1] += q0 * kf.y;
            s[0][2] += q0 * kf.z; s[0][3] += q0 * kf.w;
            s[1][0] += q1 * kf.x; s[1][1] += q1 * kf.y;
            s[1][2] += q1 * kf.z; s[1][3] += q1 * kf.w;
            s[2][0] += q2 * kf.x; s[2][1] += q2 * kf.y;
            s[2][2] += q2 * kf.z; s[2][3] += q2 * kf.w;
            s[3][0] += q3 * kf.x; s[3][1] += q3 * kf.y;
            s[3][2] += q3 * kf.z; s[3][3] += q3 * kf.w;
        }

        // ---- scale + causal mask + online softmax ----
#pragma unroll
        for (int rr = 0; rr < 4; rr++) {
            const int row = row0 + 4 * tr + rr;
#pragma unroll
            for (int cc = 0; cc < 4; cc++) {
                const int col = col0 + 4 * tc + cc;
                s[rr][cc] = s[rr][cc] * 0.25f + (col > row ? -10000000.0f : 0.0f);
            }
            // row max across this thread's 4 cols, then across 16 tc lanes
            float mx = fmaxf(fmaxf(s[rr][0], s[rr][1]), fmaxf(s[rr][2], s[rr][3]));
            mx = fmaxf(mx, __shfl_xor_sync(0xffffffffu, mx, 1));
            mx = fmaxf(mx, __shfl_xor_sync(0xffffffffu, mx, 2));
            mx = fmaxf(mx, __shfl_xor_sync(0xffffffffu, mx, 4));
            mx = fmaxf(mx, __shfl_xor_sync(0xffffffffu, mx, 8));
            const float m_new = fmaxf(m_prev[rr], mx);
            const float alpha = __expf(m_prev[rr] - m_new);

            float rs = 0.f;
#pragma unroll
            for (int cc = 0; cc < 4; cc++) {
                s[rr][cc] = __expf(s[rr][cc] - m_new);
                rs += s[rr][cc];
            }
            rs += __shfl_xor_sync(0xffffffffu, rs, 1);
            rs += __shfl_xor_sync(0xffffffffu, rs, 2);
            rs += __shfl_xor_sync(0xffffffffu, rs, 4);
            rs += __shfl_xor_sync(0xffffffffu, rs, 8);

            l_run[rr]  = l_run[rr] * alpha + rs;
            acc[rr].x *= alpha; acc[rr].y *= alpha;
            acc[rr].z *= alpha; acc[rr].w *= alpha;
            m_prev[rr] = m_new;
        }

        // ---- store P into the Kt buffer (all reads of Kt-as-K are done) ----
        __syncthreads();
#pragma unroll
        for (int rr = 0; rr < 4; rr++)
            ((float4*)Kt[4 * tr + rr])[tc] =
                make_float4(s[rr][0], s[rr][1], s[rr][2], s[rr][3]);
        __syncthreads();

        // ---- O += P * V ----
#pragma unroll 4
        for (int c = 0; c < BN; c++) {
            const float4 v = ((const float4*)Vs[c])[tc];
            const float p0 = Kt[4 * tr + 0][c];
            const float p1 = Kt[4 * tr + 1][c];
            const float p2 = Kt[4 * tr + 2][c];
            const float p3 = Kt[4 * tr + 3][c];
            acc[0].x += p0 * v.x; acc[0].y += p0 * v.y;
            acc[0].z += p0 * v.z; acc[0].w += p0 * v.w;
            acc[1].x += p1 * v.x; acc[1].y += p1 * v.y;
            acc[1].z += p1 * v.z; acc[1].w += p1 * v.w;
            acc[2].x += p2 * v.x; acc[2].y += p2 * v.y;
            acc[2].z += p2 * v.z; acc[2].w += p2 * v.w;
            acc[3].x += p3 * v.x; acc[3].y += p3 * v.y;
            acc[3].z += p3 * v.z; acc[3].w += p3 * v.w;
        }
    }

    // ---- normalize and write O ----
#pragma unroll
    for (int rr = 0; rr < 4; rr++) {
        const float inv = 1.0f / l_run[rr];
        const float4 o = make_float4(acc[rr].x * inv, acc[rr].y * inv,
                                     acc[rr].z * inv, acc[rr].w * inv);
        ((float4*)(Ob + (size_t)(row0 + 4 * tr + rr) * DH))[tc] = o;
    }
}

extern "C" void kernel_launch(void* const* d_in, const int* in_sizes, int n_in,
                              void* d_out, int out_size) {
    const float* Q = (const float*)d_in[0];
    const float* K = (const float*)d_in[1];
    const float* V = (const float*)d_in[2];
    float*       O = (float*)d_out;

    const int BH = in_sizes[0] / (L_SEQ * DH);   // 32 for [2,16,2048,64]
    dim3 grid(L_SEQ / BM, BH);
    fa_kernel<<<grid, 256>>>(Q, K, V, O);
}